// round 9
// baseline (speedup 1.0000x reference)
#include <cuda_runtime.h>
#include <cuda_fp16.h>
#include <cstdint>

// ---------------------------------------------------------------------------
// DFine Multiscale Deformable Attention
//   B=16, Q=300, HIDDEN=256, N_HEADS=8, d=32
//   SPATIAL = (100,100),(50,50),(25,25),(13,13)  -> S=13294
//   NUM_POINTS = 4 per level -> p_total=16, total_points = 128
// Output = concat( out[B,Q,256], aw[B,Q,8,16] )  (float32)
// ---------------------------------------------------------------------------

#define NB        16
#define NQ        300
#define NBQ       (NB * NQ)          // 4800
#define HIDDEN    256
#define NHEADS    8
#define PTOT      16
#define NOUT0     (NBQ * HIDDEN)
#define SENC      13294
#define ENC_ELEMS (NB * SENC * 256)  // 54,452,224
#define ENC_F4    (ENC_ELEMS / 4)    // 13,613,056

typedef unsigned long long ull;

// per-(b,q): 8 heads * 16 points * 2 coords
__device__ float  g_loc[NBQ * NHEADS * PTOT * 2];
// fp16 copy of encoder states (built by converter blocks of kernel A)
__device__ __half g_enc_h[ENC_ELEMS];          // ~104 MB? no: 54.4M * 2B = 109MB? -> see note

// NOTE: ENC_ELEMS halfs = 108.9 MB?? -> 54,452,224 * 2 B = 108.9 MB. Wrong!
// 54,452,224 elements * 2 bytes = 108,904,448 bytes = 103.8 MiB. That's the
// fp16 buffer size (the fp32 original is 217.8 MB?!). Recheck: 16*13294*256 =
// 54,452,224 elements. fp32 = 217.8 MB. fp16 = 108.9 MB.  (The "54 MB" in
// comments elsewhere undercounted by 4x.) Still fine as a __device__ array.

__device__ __forceinline__ ull pk2(float lo, float hi) {
    ull r; asm("mov.b64 %0, {%1,%2};" : "=l"(r) : "f"(lo), "f"(hi)); return r;
}
__device__ __forceinline__ void upk2(float& lo, float& hi, ull v) {
    asm("mov.b64 {%0,%1}, %2;" : "=f"(lo), "=f"(hi) : "l"(v));
}
#define FFMA2(d, a, b) asm("fma.rn.f32x2 %0, %1, %2, %0;" : "+l"(d) : "l"(a), "l"(b))

// ---------------------------------------------------------------------------
// Kernel A: blocks [0,300): projection GEMM + softmax + sampling locations
//           (R4 version — best measured).
//           blocks [300,300+NCONV): stream-convert enc fp32 -> fp16.
// The converter blocks are DRAM-bound and overlap the FMA-bound proj blocks.
// ---------------------------------------------------------------------------
#define GTILE  16
#define NPROJ  (NBQ / GTILE)         // 300
#define NCONV  96

__global__ __launch_bounds__(384, 2)
void dfine_proj_kernel(const float* __restrict__ hs,        // (BQ, 256)
                       const float* __restrict__ enc,       // (B, S, 256)
                       const float* __restrict__ ref,       // (BQ, 4)
                       const float* __restrict__ W_off,     // (256, 256)
                       const float* __restrict__ b_off,     // (256,)
                       const float* __restrict__ W_attn,    // (256, 128)
                       const float* __restrict__ b_attn,    // (128,)
                       float* __restrict__ out_aw)          // d_out + NOUT0
{
    const int tid = threadIdx.x;              // 0..383

    if (blockIdx.x >= NPROJ) {
        // ---- converter block: fp32 enc -> fp16 g_enc_h ----
        const int    base   = (blockIdx.x - NPROJ) * 384 + tid;
        const int    stride = NCONV * 384;
        uint2* dst = (uint2*)g_enc_h;
#pragma unroll 4
        for (int i = base; i < ENC_F4; i += stride) {
            const float4 v = __ldg((const float4*)enc + i);
            __half2 h0 = __floats2half2_rn(v.x, v.y);
            __half2 h1 = __floats2half2_rn(v.z, v.w);
            uint2 o;
            o.x = *reinterpret_cast<unsigned*>(&h0);
            o.y = *reinterpret_cast<unsigned*>(&h1);
            dst[i] = o;
        }
        return;
    }

    __shared__ ull shP[8 * 256];              // [gp][k]: pack(hs[2gp][k], hs[2gp+1][k])
    const int bq0 = blockIdx.x * GTILE;

    const float* hsb = hs + (size_t)bq0 * HIDDEN;
    for (int i = tid; i < 8 * 256; i += 384) {
        const int gp = i >> 8, k = i & 255;
        shP[gp * 256 + k] = pk2(hsb[(2 * gp) * 256 + k], hsb[(2 * gp + 1) * 256 + k]);
    }
    __syncthreads();

    const bool is_off = (tid < 256);
    const float* Wp = is_off ? (W_off + tid) : (W_attn + (tid - 256));
    const int    ws = is_off ? 256 : 128;
    const float  bias = is_off ? b_off[tid] : b_attn[tid - 256];

    ull acc2[8];
#pragma unroll
    for (int gp = 0; gp < 8; ++gp) acc2[gp] = pk2(bias, bias);

    float w[8];
#pragma unroll
    for (int j = 0; j < 8; ++j) w[j] = __ldg(Wp + (size_t)j * ws);

#pragma unroll 1
    for (int k0 = 0; k0 < HIDDEN; k0 += 8) {
        float wn[8];
        const bool more = (k0 + 8) < HIDDEN;
#pragma unroll
        for (int j = 0; j < 8; ++j)
            wn[j] = more ? __ldg(Wp + (size_t)(k0 + 8 + j) * ws) : 0.0f;

        ull wd[8];
#pragma unroll
        for (int j = 0; j < 8; ++j) wd[j] = pk2(w[j], w[j]);

#pragma unroll
        for (int gp = 0; gp < 8; ++gp) {
            const ull* row = shP + gp * 256 + k0;
#pragma unroll
            for (int jj = 0; jj < 4; ++jj) {
                const ulonglong2 p = *(const ulonglong2*)(row + 2 * jj);
                FFMA2(acc2[gp], p.x, wd[2 * jj]);
                FFMA2(acc2[gp], p.y, wd[2 * jj + 1]);
            }
        }
#pragma unroll
        for (int j = 0; j < 8; ++j) w[j] = wn[j];
    }

    float acc[GTILE];
#pragma unroll
    for (int gp = 0; gp < 8; ++gp)
        upk2(acc[2 * gp], acc[2 * gp + 1], acc2[gp]);

    if (!is_off) {
        // softmax over the 16 points of each head (16-lane groups)
        const int idx = tid - 256;            // h*16 + p
#pragma unroll
        for (int g = 0; g < GTILE; ++g) {
            float v = acc[g];
            float m = v;
#pragma unroll
            for (int o = 8; o; o >>= 1)
                m = fmaxf(m, __shfl_xor_sync(0xffffffffu, m, o));
            float e = __expf(v - m);
            float s = e;
#pragma unroll
            for (int o = 8; o; o >>= 1)
                s += __shfl_xor_sync(0xffffffffu, s, o);
            out_aw[(size_t)(bq0 + g) * (NHEADS * PTOT) + idx] = e / s;
        }
    } else {
        // sampling locations: loc = ref_xy + acc * (1/4) * 0.5 * ref_wh
        const int c = tid & 1;
#pragma unroll
        for (int g = 0; g < GTILE; ++g) {
            const float4 r = __ldg((const float4*)ref + (bq0 + g));
            const float base = c ? r.y : r.x;
            const float wh   = c ? r.w : r.z;
            g_loc[(size_t)(bq0 + g) * 256 + tid] = fmaf(acc[g] * 0.125f, wh, base);
        }
    }
}

// ---------------------------------------------------------------------------
// Kernel B: bilinear sampling + weighted sum on fp16 values.
// QB=8 queries per block (grid 600), double-buffered tap setup (R8 skeleton).
// Lane layout: lane = pp(2) x tap(4) x chanoctet(4) -> one LDG.128 covers
// 2 points x 4 taps x 8 channels; only 8 LDG per (query, head).
// Reduction over pp+tap via 3 shuffle rounds; lanes 0..3 store 8 ch each.
// ---------------------------------------------------------------------------
#define QB 8

__global__ __launch_bounds__(256)
void dfine_sample_kernel(const float* __restrict__ aw,      // (BQ, 128)
                         float* __restrict__ out)           // (BQ, 256)
{
    __shared__ int2 s_tap[2][512];            // [buf][hp*4 + tap]

    const int bq0 = blockIdx.x * QB;
    const int tid = threadIdx.x;

    // this thread's two tap-setup tasks (task = half*256 + tid)
    const int task0 = tid,        hp0 = task0 >> 2, t0 = task0 & 3;
    const int task1 = tid + 256,  hp1 = task1 >> 2, t1 = task1 & 3;

    const int lvl0 = (hp0 & 15) >> 2, lvl1 = (hp1 & 15) >> 2;
    const int w0_  = (lvl0 == 0) ? 100 : (lvl0 == 1) ? 50 : (lvl0 == 2) ? 25 : 13;
    const int w1_  = (lvl1 == 0) ? 100 : (lvl1 == 1) ? 50 : (lvl1 == 2) ? 25 : 13;
    const int st0  = (lvl0 == 0) ? 0 : (lvl0 == 1) ? 10000 : (lvl0 == 2) ? 12500 : 13125;
    const int st1  = (lvl1 == 0) ? 0 : (lvl1 == 1) ? 10000 : (lvl1 == 2) ? 12500 : 13125;

    // compute-phase constants
    const int h    = tid >> 5;                // warp = head
    const int lane = tid & 31;
    const int pp   = lane >> 4;               // point parity (0/1)
    const int t    = (lane >> 2) & 3;         // tap 0..3
    const int co   = lane & 3;                // channel octet 0..3

    auto tap_make = [](int hp, int tp, int w, int st, float2 l2, float a) -> int2 {
        const float x = fmaf(l2.x, (float)w, -0.5f);
        const float y = fmaf(l2.y, (float)w, -0.5f);
        const float x0f = floorf(x), y0f = floorf(y);
        const float wx1 = x - x0f, wy1 = y - y0f;
        const int tx = tp & 1, ty = tp >> 1;
        const int xi = (int)x0f + tx;
        const int yi = (int)y0f + ty;
        const bool valid = (xi >= 0) && (xi < w) && (yi >= 0) && (yi < w);
        const float wt = (ty ? wy1 : 1.0f - wy1) * (tx ? wx1 : 1.0f - wx1) * a;
        const int off = st * 256 + (hp >> 4) * 32 + (yi * w + xi) * 256;
        return make_int2(valid ? off : 0, __float_as_int(valid ? wt : 0.0f));
    };

    // ---- prologue: setup bq0 into buf 0 ----
    {
        float2 l0 = ((const float2*)g_loc)[(size_t)bq0 * 128 + hp0];
        float2 l1 = ((const float2*)g_loc)[(size_t)bq0 * 128 + hp1];
        float  a0 = aw[(size_t)bq0 * 128 + hp0];
        float  a1 = aw[(size_t)bq0 * 128 + hp1];
        s_tap[0][task0] = tap_make(hp0, t0, w0_, st0, l0, a0);
        s_tap[0][task1] = tap_make(hp1, t1, w1_, st1, l1, a1);
    }

#pragma unroll 1
    for (int i = 0; i < QB; ++i) {
        __syncthreads();
        const int bq  = bq0 + i;
        const int buf = i & 1;

        // issue next query's setup loads first (latency overlapped below)
        float2 nl0, nl1; float na0, na1;
        if (i + 1 < QB) {
            const int nbq = bq + 1;
            nl0 = ((const float2*)g_loc)[(size_t)nbq * 128 + hp0];
            nl1 = ((const float2*)g_loc)[(size_t)nbq * 128 + hp1];
            na0 = aw[(size_t)nbq * 128 + hp0];
            na1 = aw[(size_t)nbq * 128 + hp1];
        }

        // ---- fp16 gather for current query ----
        const int b = bq / NQ;
        const __half* encb = g_enc_h + (size_t)b * (SENC * 256) + co * 8;
        const int2* tb = &s_tap[buf][h * 64 + pp * 4 + t];   // entry for (h, p=pp, t)

        // fetch 8 tap descriptors (points p = 2j + pp), then 8 batched loads
        int   idx[8];
        float wt[8];
#pragma unroll
        for (int j = 0; j < 8; ++j) {
            const int2 tp = tb[j * 8];        // advance p by 2 -> 8 int2 entries
            idx[j] = tp.x;
            wt[j]  = __int_as_float(tp.y);
        }
        uint4 v[8];
#pragma unroll
        for (int j = 0; j < 8; ++j)
            v[j] = __ldg((const uint4*)(encb + idx[j]));

        float acc[8];
#pragma unroll
        for (int c = 0; c < 8; ++c) acc[c] = 0.0f;
#pragma unroll
        for (int j = 0; j < 8; ++j) {
            const float wj = wt[j];
            float2 f;
            f = __half22float2(*reinterpret_cast<const __half2*>(&v[j].x));
            acc[0] = fmaf(wj, f.x, acc[0]); acc[1] = fmaf(wj, f.y, acc[1]);
            f = __half22float2(*reinterpret_cast<const __half2*>(&v[j].y));
            acc[2] = fmaf(wj, f.x, acc[2]); acc[3] = fmaf(wj, f.y, acc[3]);
            f = __half22float2(*reinterpret_cast<const __half2*>(&v[j].z));
            acc[4] = fmaf(wj, f.x, acc[4]); acc[5] = fmaf(wj, f.y, acc[5]);
            f = __half22float2(*reinterpret_cast<const __half2*>(&v[j].w));
            acc[6] = fmaf(wj, f.x, acc[6]); acc[7] = fmaf(wj, f.y, acc[7]);
        }

        // reduce over tap (xor 4, 8) and point-parity (xor 16)
#pragma unroll
        for (int o = 4; o <= 16; o <<= 1) {
#pragma unroll
            for (int c = 0; c < 8; ++c)
                acc[c] += __shfl_xor_sync(0xffffffffu, acc[c], o);
        }

        if (lane < 4) {       // lane == co, holds channels co*8 .. co*8+7
            float4 r0, r1;
            r0.x = acc[0]; r0.y = acc[1]; r0.z = acc[2]; r0.w = acc[3];
            r1.x = acc[4]; r1.y = acc[5]; r1.z = acc[6]; r1.w = acc[7];
            float* op = out + (size_t)bq * 256 + h * 32 + lane * 8;
            *(float4*)op       = r0;
            *(float4*)(op + 4) = r1;
        }

        // ---- setup next query into the other buffer ----
        if (i + 1 < QB) {
            s_tap[buf ^ 1][task0] = tap_make(hp0, t0, w0_, st0, nl0, na0);
            s_tap[buf ^ 1][task1] = tap_make(hp1, t1, w1_, st1, nl1, na1);
        }
    }
}

// ---------------------------------------------------------------------------
extern "C" void kernel_launch(void* const* d_in, const int* in_sizes, int n_in,
                              void* d_out, int out_size)
{
    const float* hs     = (const float*)d_in[0];   // (B,Q,256)
    const float* enc    = (const float*)d_in[1];   // (B,S,256)
    const float* ref    = (const float*)d_in[2];   // (B,Q,1,4)
    const float* W_off  = (const float*)d_in[3];   // (256,256)
    const float* b_off  = (const float*)d_in[4];   // (256,)
    const float* W_attn = (const float*)d_in[5];   // (256,128)
    const float* b_attn = (const float*)d_in[6];   // (128,)

    float* out    = (float*)d_out;                 // (B,Q,256)
    float* out_aw = (float*)d_out + NOUT0;         // (B,Q,8,16)

    dfine_proj_kernel<<<NPROJ + NCONV, 384>>>(hs, enc, ref, W_off, b_off,
                                              W_attn, b_attn, out_aw);
    dfine_sample_kernel<<<NBQ / QB, 256>>>(out_aw, out);
}

// round 13
// speedup vs baseline: 2.8208x; 2.8208x over previous
#include <cuda_runtime.h>
#include <cstdint>

// ---------------------------------------------------------------------------
// DFine Multiscale Deformable Attention
//   B=16, Q=300, HIDDEN=256, N_HEADS=8, d=32
//   SPATIAL = (100,100),(50,50),(25,25),(13,13)  -> S=13294
//   NUM_POINTS = 4 per level -> p_total=16, total_points = 128
// Output = concat( out[B,Q,256], aw[B,Q,8,16] )  (float32)
// ---------------------------------------------------------------------------

#define NB        16
#define NQ        300
#define NBQ       (NB * NQ)          // 4800
#define HIDDEN    256
#define NHEADS    8
#define PTOT      16
#define NOUT0     (NBQ * HIDDEN)
#define SENC      13294

// per-(b,q): 8 heads * 16 points * 2 coords
__device__ float g_loc[NBQ * 256];

// ---------------- small PTX helpers ----------------
__device__ __forceinline__ void cp_async16(void* smem_dst, const void* gsrc) {
    unsigned sd = (unsigned)__cvta_generic_to_shared(smem_dst);
    asm volatile("cp.async.ca.shared.global [%0], [%1], 16;" :: "r"(sd), "l"(gsrc));
}
__device__ __forceinline__ void cp_commit() {
    asm volatile("cp.async.commit_group;");
}
template <int N>
__device__ __forceinline__ void cp_wait() {
    asm volatile("cp.async.wait_group %0;" :: "n"(N));
}
__device__ __forceinline__ uint32_t cvt_tf32(float x) {
    uint32_t r; asm("cvt.rna.tf32.f32 %0, %1;" : "=r"(r) : "f"(x)); return r;
}
__device__ __forceinline__ void mma_tf32(float* d, const uint32_t* a, const uint32_t* b) {
    asm("mma.sync.aligned.m16n8k8.row.col.f32.tf32.tf32.f32 "
        "{%0,%1,%2,%3}, {%4,%5,%6,%7}, {%8,%9}, {%0,%1,%2,%3};"
        : "+f"(d[0]), "+f"(d[1]), "+f"(d[2]), "+f"(d[3])
        : "r"(a[0]), "r"(a[1]), "r"(a[2]), "r"(a[3]), "r"(b[0]), "r"(b[1]));
}

// ---------------------------------------------------------------------------
// Kernel A: projection via tf32 mma.sync + softmax + sampling locations.
// Grid 300 = 150 m-tiles (M=32 rows) x 2 n-halves (N=192 cols of 384).
// 256 threads = 8 warps, warp tile m32 x n24 (2 m-subtiles x 3 n-subtiles).
// K=256 streamed in 8-row chunks via 2-stage cp.async.
// ---------------------------------------------------------------------------
#define MT      32
#define NCB     192
#define KC      8
#define NCHUNK  (HIDDEN / KC)        // 32

struct ProjSmem {
    float A[MT][256];                // XOR-swizzled (col ^= (row&7)<<2)
    float Wst[2][KC][200];           // pad 200 -> conflict-free B frags
};

__global__ __launch_bounds__(256, 2)
void dfine_proj_kernel(const float* __restrict__ hs,        // (BQ, 256)
                       const float* __restrict__ ref,       // (BQ, 4)
                       const float* __restrict__ W_off,     // (256, 256)
                       const float* __restrict__ b_off,     // (256,)
                       const float* __restrict__ W_attn,    // (256, 128)
                       const float* __restrict__ b_attn,    // (128,)
                       float* __restrict__ out_aw)          // d_out + NOUT0
{
    __shared__ __align__(16) char smraw[sizeof(ProjSmem)];  // 44.5 KB
    ProjSmem* ps = reinterpret_cast<ProjSmem*>(smraw);
    float (*C)[NCB] = reinterpret_cast<float (*)[NCB]>(smraw);

    const int tid = threadIdx.x;
    const int w   = tid >> 5;
    const int l   = tid & 31;
    const int mt  = blockIdx.x >> 1;
    const int cb  = blockIdx.x & 1;
    const int bq0 = mt * MT;

    // ---- load A (32 hs rows) with XOR swizzle ----
    {
        const float4* src = (const float4*)(hs + (size_t)bq0 * 256);
#pragma unroll
        for (int j = 0; j < 8; ++j) {
            const int idx = tid + j * 256;           // 0..2047
            const int r = idx >> 6, c4 = idx & 63;
            const float4 v = __ldg(src + idx);
            const int col = (c4 * 4) ^ ((r & 7) << 2);
            *(float4*)&ps->A[r][col] = v;
        }
    }

    // ---- W chunk loader: 8 rows x 48 float4 into Wst[stg] ----
    auto issue_chunk = [&](int c, int stg) {
        const int k0 = c * KC;
#pragma unroll
        for (int q = 0; q < 2; ++q) {
            const int f = tid + q * 256;
            if (f < 384) {
                const int kr = f / 48, cf = f % 48;
                const int gc4 = cb * 48 + cf;        // global float4 column
                const float* src = (gc4 < 64)
                    ? (W_off  + (size_t)(k0 + kr) * 256 + gc4 * 4)
                    : (W_attn + (size_t)(k0 + kr) * 128 + (gc4 - 64) * 4);
                cp_async16(&ps->Wst[stg][kr][cf * 4], src);
            }
        }
    };

    float d[6][4];
#pragma unroll
    for (int i = 0; i < 6; ++i)
#pragma unroll
        for (int j = 0; j < 4; ++j) d[i][j] = 0.0f;

    issue_chunk(0, 0);
    cp_commit();

#pragma unroll 1
    for (int c = 0; c < NCHUNK; ++c) {
        if (c + 1 < NCHUNK) issue_chunk(c + 1, (c + 1) & 1);
        cp_commit();
        cp_wait<1>();
        __syncthreads();

        const int stg = c & 1;
        const int k0  = c * KC;

        // A fragments (conflict-free via XOR swizzle)
        uint32_t a[2][4];
#pragma unroll
        for (int ms = 0; ms < 2; ++ms) {
            const int r0 = ms * 16 + (l >> 2);
            const int sw = (r0 & 7) << 2;            // (r0+8)&7 == r0&7
            const int cA = k0 + (l & 3);
            a[ms][0] = cvt_tf32(ps->A[r0    ][ cA      ^ sw]);
            a[ms][1] = cvt_tf32(ps->A[r0 + 8][ cA      ^ sw]);
            a[ms][2] = cvt_tf32(ps->A[r0    ][(cA + 4) ^ sw]);
            a[ms][3] = cvt_tf32(ps->A[r0 + 8][(cA + 4) ^ sw]);
        }
        // B fragments
        uint32_t b[3][2];
#pragma unroll
        for (int ns = 0; ns < 3; ++ns) {
            const int n = w * 24 + ns * 8 + (l >> 2);
            b[ns][0] = cvt_tf32(ps->Wst[stg][ l & 3     ][n]);
            b[ns][1] = cvt_tf32(ps->Wst[stg][(l & 3) + 4][n]);
        }
#pragma unroll
        for (int ms = 0; ms < 2; ++ms)
#pragma unroll
            for (int ns = 0; ns < 3; ++ns)
                mma_tf32(d[ms * 3 + ns], a[ms], b[ns]);

        __syncthreads();   // protect Wst/A before next-stage overwrite
    }

    // ---- write accumulators to C tile (reuses A/Wst memory) ----
#pragma unroll
    for (int ms = 0; ms < 2; ++ms)
#pragma unroll
        for (int ns = 0; ns < 3; ++ns) {
            const int r  = ms * 16 + (l >> 2);
            const int cc = w * 24 + ns * 8 + 2 * (l & 3);
            const float* D = d[ms * 3 + ns];
            C[r    ][cc]     = D[0];
            C[r    ][cc + 1] = D[1];
            C[r + 8][cc]     = D[2];
            C[r + 8][cc + 1] = D[3];
        }
    __syncthreads();

    // ---- epilogue: 192 active threads, one column each ----
    if (tid < NCB) {
        if (cb == 0 || tid < 64) {
            // offset column: col in [0,256)
            const int col = cb * 192 + tid;
            const float bo = __ldg(b_off + col);
            const int cxy = col & 1;
#pragma unroll 4
            for (int r = 0; r < MT; ++r) {
                const float4 rf = __ldg((const float4*)ref + (bq0 + r));
                const float base = cxy ? rf.y : rf.x;
                const float wh   = cxy ? rf.w : rf.z;
                const float val  = C[r][tid] + bo;
                g_loc[(size_t)(bq0 + r) * 256 + col] = fmaf(val * 0.125f, wh, base);
            }
        } else {
            // attn column: idx in [0,128); warps 2..5 fully in this branch
            const int idx = tid - 64;
            const float ba = __ldg(b_attn + idx);
#pragma unroll 2
            for (int r = 0; r < MT; ++r) {
                const float v = C[r][tid] + ba;
                float m = v;
#pragma unroll
                for (int o = 8; o; o >>= 1)
                    m = fmaxf(m, __shfl_xor_sync(0xffffffffu, m, o));
                const float e = __expf(v - m);
                float s = e;
#pragma unroll
                for (int o = 8; o; o >>= 1)
                    s += __shfl_xor_sync(0xffffffffu, s, o);
                out_aw[(size_t)(bq0 + r) * 128 + idx] = e / s;
            }
        }
    }
}

// ---------------------------------------------------------------------------
// Kernel B: bilinear sampling + weighted sum (R8 version — best measured).
// QB=8 queries per block (grid 600), double-buffered tap setup.
// Per query: warp = head; lane = tap(4) x chanquad(8); 2x front-batched
// 8-deep LDG.128; cross-tap shuffle reduction.
// ---------------------------------------------------------------------------
#define QB 8

__global__ __launch_bounds__(256)
void dfine_sample_kernel(const float* __restrict__ enc,     // (B, S, 256)
                         const float* __restrict__ aw,      // (BQ, 128)
                         float* __restrict__ out)           // (BQ, 256)
{
    __shared__ int2 s_tap[2][512];            // [buf][hp*4 + tap]

    const int bq0 = blockIdx.x * QB;
    const int tid = threadIdx.x;

    const int task0 = tid,        hp0 = task0 >> 2, t0 = task0 & 3;
    const int task1 = tid + 256,  hp1 = task1 >> 2, t1 = task1 & 3;

    const int lvl0 = (hp0 & 15) >> 2, lvl1 = (hp1 & 15) >> 2;
    const int w0_  = (lvl0 == 0) ? 100 : (lvl0 == 1) ? 50 : (lvl0 == 2) ? 25 : 13;
    const int w1_  = (lvl1 == 0) ? 100 : (lvl1 == 1) ? 50 : (lvl1 == 2) ? 25 : 13;
    const int st0  = (lvl0 == 0) ? 0 : (lvl0 == 1) ? 10000 : (lvl0 == 2) ? 12500 : 13125;
    const int st1  = (lvl1 == 0) ? 0 : (lvl1 == 1) ? 10000 : (lvl1 == 2) ? 12500 : 13125;

    const int h    = tid >> 5;                // warp = head
    const int lane = tid & 31;
    const int t    = lane >> 3;               // tap 0..3
    const int dq   = (lane & 7) << 2;         // channel quad start

    auto tap_make = [](int hp, int tp, int w, int st, float2 l2, float a) -> int2 {
        const float x = fmaf(l2.x, (float)w, -0.5f);
        const float y = fmaf(l2.y, (float)w, -0.5f);
        const float x0f = floorf(x), y0f = floorf(y);
        const float wx1 = x - x0f, wy1 = y - y0f;
        const int tx = tp & 1, ty = tp >> 1;
        const int xi = (int)x0f + tx;
        const int yi = (int)y0f + ty;
        const bool valid = (xi >= 0) && (xi < w) && (yi >= 0) && (yi < w);
        const float wt = (ty ? wy1 : 1.0f - wy1) * (tx ? wx1 : 1.0f - wx1) * a;
        const int off = st * 256 + (hp >> 4) * 32 + (yi * w + xi) * 256;
        return make_int2(valid ? off : 0, __float_as_int(valid ? wt : 0.0f));
    };

    {
        float2 l0 = ((const float2*)g_loc)[(size_t)bq0 * 128 + hp0];
        float2 l1 = ((const float2*)g_loc)[(size_t)bq0 * 128 + hp1];
        float  a0 = aw[(size_t)bq0 * 128 + hp0];
        float  a1 = aw[(size_t)bq0 * 128 + hp1];
        s_tap[0][task0] = tap_make(hp0, t0, w0_, st0, l0, a0);
        s_tap[0][task1] = tap_make(hp1, t1, w1_, st1, l1, a1);
    }

#pragma unroll 1
    for (int i = 0; i < QB; ++i) {
        __syncthreads();
        const int bq  = bq0 + i;
        const int buf = i & 1;

        float2 nl0, nl1; float na0, na1;
        if (i + 1 < QB) {
            const int nbq = bq + 1;
            nl0 = ((const float2*)g_loc)[(size_t)nbq * 128 + hp0];
            nl1 = ((const float2*)g_loc)[(size_t)nbq * 128 + hp1];
            na0 = aw[(size_t)nbq * 128 + hp0];
            na1 = aw[(size_t)nbq * 128 + hp1];
        }

        const int b = bq / NQ;
        const float* encb = enc + (size_t)b * (SENC * 256) + dq;
        const int2* tb = &s_tap[buf][h * PTOT * 4 + t];

        float ax = 0.f, ay = 0.f, az = 0.f, aq = 0.f;
#pragma unroll
        for (int pb = 0; pb < PTOT; pb += 8) {
            int   idx[8];
            float wt[8];
#pragma unroll
            for (int j = 0; j < 8; ++j) {
                const int2 tp = tb[(pb + j) * 4];
                idx[j] = tp.x;
                wt[j]  = __int_as_float(tp.y);
            }
            float4 v[8];
#pragma unroll
            for (int j = 0; j < 8; ++j)
                v[j] = __ldg((const float4*)(encb + idx[j]));
#pragma unroll
            for (int j = 0; j < 8; ++j) {
                ax = fmaf(wt[j], v[j].x, ax);
                ay = fmaf(wt[j], v[j].y, ay);
                az = fmaf(wt[j], v[j].z, az);
                aq = fmaf(wt[j], v[j].w, aq);
            }
        }

#pragma unroll
        for (int o = 8; o <= 16; o <<= 1) {
            ax += __shfl_xor_sync(0xffffffffu, ax, o);
            ay += __shfl_xor_sync(0xffffffffu, ay, o);
            az += __shfl_xor_sync(0xffffffffu, az, o);
            aq += __shfl_xor_sync(0xffffffffu, aq, o);
        }
        if (lane < 8) {
            float4 r;
            r.x = ax; r.y = ay; r.z = az; r.w = aq;
            *(float4*)(out + (size_t)bq * 256 + h * 32 + dq) = r;
        }

        if (i + 1 < QB) {
            s_tap[buf ^ 1][task0] = tap_make(hp0, t0, w0_, st0, nl0, na0);
            s_tap[buf ^ 1][task1] = tap_make(hp1, t1, w1_, st1, nl1, na1);
        }
    }
}

// ---------------------------------------------------------------------------
extern "C" void kernel_launch(void* const* d_in, const int* in_sizes, int n_in,
                              void* d_out, int out_size)
{
    const float* hs     = (const float*)d_in[0];   // (B,Q,256)
    const float* enc    = (const float*)d_in[1];   // (B,S,256)
    const float* ref    = (const float*)d_in[2];   // (B,Q,1,4)
    const float* W_off  = (const float*)d_in[3];   // (256,256)
    const float* b_off  = (const float*)d_in[4];   // (256,)
    const float* W_attn = (const float*)d_in[5];   // (256,128)
    const float* b_attn = (const float*)d_in[6];   // (128,)

    float* out    = (float*)d_out;                 // (B,Q,256)
    float* out_aw = (float*)d_out + NOUT0;         // (B,Q,8,16)

    dfine_proj_kernel<<<(NBQ / MT) * 2, 256>>>(hs, ref, W_off, b_off, W_attn,
                                               b_attn, out_aw);
    dfine_sample_kernel<<<NBQ / QB, 256>>>(enc, out_aw, out);
}